// round 17
// baseline (speedup 1.0000x reference)
#include <cuda_runtime.h>
#include <cuda_fp16.h>
#include <math.h>

// ---------------- scratch ----------------
__device__ float g_f1[32u * 32 * 128 * 128];              // fp32 NCHW (e6 out)
__device__ unsigned short g_b0[33554432];                 // fp16 planes ping [px][C]
__device__ unsigned short g_b1[33554432];                 // fp16 planes pong
__device__ uint4 g_wprep[60480];                          // s1 mma weights (fp16 hi/lo)
__device__ uint4 g_wprep0[1152];                          // e0 mma weights (C=16 padded)
__device__ uint4 g_wprep2[106496];                        // s2c mma weights
__device__ uint4 g_wprep3[43008];                         // t2c mma weights
__device__ float g_S[4096];
__device__ float g_Sh[4096];
__device__ float g_Sw[4096];

__device__ __forceinline__ float activate(float v, int act) {
    switch (act) {
        case 1: return v > 0.f ? v : 0.2f * v;
        case 2: return v > 0.f ? v : 0.f;
        case 3: return fmaxf(v, 0.f) + log1pf(expf(-fabsf(v)));
        default: return v;
    }
}

__device__ __forceinline__ unsigned pack2_f16(float lo, float hi) {
    __half2 h = __floats2half2_rn(lo, hi);
    return *(unsigned*)&h;
}
__device__ __forceinline__ unsigned short f16_us(float x) {
    __half h = __float2half_rn(x);
    return *(unsigned short*)&h;
}

__device__ __forceinline__ void cp_async16(void* sdst, const void* gsrc, bool pred) {
    unsigned saddr = (unsigned)__cvta_generic_to_shared(sdst);
    int sz = pred ? 16 : 0;
    asm volatile("cp.async.cg.shared.global [%0], [%1], 16, %2;\n"
                 :: "r"(saddr), "l"(gsrc), "r"(sz));
}
__device__ __forceinline__ void cp_commit() { asm volatile("cp.async.commit_group;\n"); }
__device__ __forceinline__ void cp_wait0() { asm volatile("cp.async.wait_group 0;\n"); }

__device__ __forceinline__ void mma16816(float* d, const unsigned* a, unsigned b0, unsigned b1) {
    asm volatile("mma.sync.aligned.m16n8k16.row.col.f32.f16.f16.f32 "
                 "{%0,%1,%2,%3},{%4,%5,%6,%7},{%8,%9},{%0,%1,%2,%3};"
                 : "+f"(d[0]), "+f"(d[1]), "+f"(d[2]), "+f"(d[3])
                 : "r"(a[0]), "r"(a[1]), "r"(a[2]), "r"(a[3]), "r"(b0), "r"(b1));
}

// =====================================================================
// s1 weight prep (3 layers/launch): fp16 hi + fp16 residual lo
// =====================================================================
__global__ void prep_many(const float* __restrict__ w0, const float* __restrict__ w1,
                          const float* __restrict__ w2, uint4* __restrict__ dstb,
                          int off0, int off1, int off2,
                          int C0, int OC0, int C1, int OC1, int C2, int OC2)
{
    int layer = blockIdx.y;
    const float* w = layer == 0 ? w0 : layer == 1 ? w1 : w2;
    uint4* dst = dstb + (layer == 0 ? off0 : layer == 1 ? off1 : off2);
    int C = layer == 0 ? C0 : layer == 1 ? C1 : C2;
    int OC = layer == 0 ? OC0 : layer == 1 ? OC1 : OC2;
    int OCg = OC >> 3;
    int total = (C >> 4) * 9 * OCg * 32;
    int idx = blockIdx.x * 256 + threadIdx.x;
    if (idx >= total) return;
    int l = idx & 31;
    int q = idx >> 5;
    int og = q % OCg; q /= OCg;
    int t = q % 9;
    int kc = q / 9;
    int tg = l & 3, gg = l >> 2;
    int n = og * 8 + gg;
    float h[4], lo[4];
#pragma unroll
    for (int kk = 0; kk < 4; kk++) {
        int k = (kk < 2) ? (2 * tg + kk) : (2 * tg + 8 + (kk - 2));
        int ic = (kc << 4) + k;
        float e = w[((size_t)n * C + ic) * 9 + t];
        h[kk] = __half2float(__float2half_rn(e));
        lo[kk] = e - h[kk];
    }
    uint4 r;
    r.x = pack2_f16(h[0], h[1]);
    r.y = pack2_f16(h[2], h[3]);
    r.z = pack2_f16(lo[0], lo[1]);
    r.w = pack2_f16(lo[2], lo[3]);
    dst[idx] = r;
}

// =====================================================================
// e0 weight prep: C=3 real channels padded to C=16 (KC=1), OC=32, 9 taps
// =====================================================================
__global__ void prep_e0(const float* __restrict__ w, uint4* __restrict__ dst)
{
    const int C = 16, CR = 3, OC = 32;
    const int OCg = OC >> 3;
    int total = 9 * OCg * 32;      // 1152
    int idx = blockIdx.x * 256 + threadIdx.x;
    if (idx >= total) return;
    int l = idx & 31;
    int q = idx >> 5;
    int og = q % OCg;
    int t = q / OCg;               // kc = 0
    int tg = l & 3, gg = l >> 2;
    int n = og * 8 + gg;
    float h[4];
#pragma unroll
    for (int kk = 0; kk < 4; kk++) {
        int k = (kk < 2) ? (2 * tg + kk) : (2 * tg + 8 + (kk - 2));
        float e = (k < CR) ? w[((size_t)n * CR + k) * 9 + t] : 0.f;
        h[kk] = e;
    }
    uint4 r;
    r.x = pack2_f16(h[0], h[1]);
    r.y = pack2_f16(h[2], h[3]);
    r.z = 0;
    r.w = 0;
    dst[idx] = r;
    (void)C;
}

// =====================================================================
// x -> fp16 planes, 3 channels padded to 16. one thread per pixel.
// =====================================================================
__global__ void x2half(const float* __restrict__ x, unsigned short* __restrict__ bout)
{
    int px = blockIdx.x * 256 + threadIdx.x;       // 524288 total
    int b = px >> 14;
    int p = px & 16383;
    const float* xb = x + (size_t)b * 3 * 16384;
    float v0 = xb[p];
    float v1 = xb[16384 + p];
    float v2 = xb[2 * 16384 + p];
    uint4 u;
    u.x = pack2_f16(v0, v1);
    u.y = pack2_f16(v2, 0.f);
    u.z = 0;
    u.w = 0;
    *(uint4*)(bout + (size_t)px * 16) = u;
    *(uint4*)(bout + (size_t)px * 16 + 8) = make_uint4(0, 0, 0, 0);
}

// =====================================================================
// s2c weight prep
// =====================================================================
__global__ void prep_s2c(const float* __restrict__ w0, const float* __restrict__ w1,
                         const float* __restrict__ w2, uint4* __restrict__ dstb,
                         int off0, int off1, int off2,
                         int C0, int OC0, int C1, int OC1, int C2, int OC2)
{
    int layer = blockIdx.y;
    const float* w = layer == 0 ? w0 : layer == 1 ? w1 : w2;
    uint4* dst = dstb + (layer == 0 ? off0 : layer == 1 ? off1 : off2);
    int C = layer == 0 ? C0 : layer == 1 ? C1 : C2;
    int OC = layer == 0 ? OC0 : layer == 1 ? OC1 : OC2;
    int OCg = OC >> 3;
    int KC = (4 * C) >> 4;
    int total = KC * 4 * OCg * 32;
    int idx = blockIdx.x * 256 + threadIdx.x;
    if (idx >= total) return;
    int l = idx & 31;
    int q = idx >> 5;
    int og = q % OCg; q /= OCg;
    int t = q % 4;
    int kc = q / 4;
    int dy = t >> 1, dx = t & 1;
    int tg = l & 3, gg = l >> 2;
    int n = og * 8 + gg;
    float h[4];
#pragma unroll
    for (int kk = 0; kk < 4; kk++) {
        int k = (kk < 2) ? (2 * tg + kk) : (2 * tg + 8 + (kk - 2));
        int ch = (kc << 4) + k;
        int qph = ch / C, c = ch - qph * C;
        int a = qph >> 1, bph = qph & 1;
        int ky = 2 * dy + a, kx = 2 * dx + bph;
        h[kk] = (ky < 3 && kx < 3) ? w[((size_t)n * C + c) * 9 + ky * 3 + kx] : 0.f;
    }
    uint4 r;
    r.x = pack2_f16(h[0], h[1]);
    r.y = pack2_f16(h[2], h[3]);
    r.z = 0;
    r.w = 0;
    dst[idx] = r;
}

// =====================================================================
// t2c weight prep
// =====================================================================
__global__ void prep_t2c(const float* __restrict__ w0, const float* __restrict__ w1,
                         const float* __restrict__ w2, uint4* __restrict__ dstb,
                         int off0, int off1, int off2,
                         int C0, int OC0, int C1, int OC1, int C2, int OC2)
{
    int layer = blockIdx.y;
    const float* w = layer == 0 ? w0 : layer == 1 ? w1 : w2;
    uint4* dst = dstb + (layer == 0 ? off0 : layer == 1 ? off1 : off2);
    int C = layer == 0 ? C0 : layer == 1 ? C1 : C2;
    int OC = layer == 0 ? OC0 : layer == 1 ? OC1 : OC2;
    int NN = 4 * OC;
    int OCgN = NN >> 3;
    int KC = C >> 4;
    int total = KC * 4 * OCgN * 32;
    int idx = blockIdx.x * 256 + threadIdx.x;
    if (idx >= total) return;
    int l = idx & 31;
    int q = idx >> 5;
    int og = q % OCgN; q /= OCgN;
    int t = q % 4;
    int kc = q / 4;
    int u = t >> 1, v = t & 1;
    int tg = l & 3, gg = l >> 2;
    int n = og * 8 + gg;
    int qph = n / OC, oc = n - qph * OC;
    int a = qph >> 1, bph = qph & 1;
    int ky = 2 * u - a, kx = 2 * v - bph;
    float h[4];
#pragma unroll
    for (int kk = 0; kk < 4; kk++) {
        int k = (kk < 2) ? (2 * tg + kk) : (2 * tg + 8 + (kk - 2));
        int c = (kc << 4) + k;
        h[kk] = (ky >= 0 && kx >= 0) ? w[((size_t)oc * C + c) * 9 + ky * 3 + kx] : 0.f;
    }
    uint4 r;
    r.x = pack2_f16(h[0], h[1]);
    r.y = pack2_f16(h[2], h[3]);
    r.z = 0;
    r.w = 0;
    dst[idx] = r;
}

// =====================================================================
// tensor-core stride-1 3x3 SAME conv (fp16 single-term). Templated NF.
// in: fp16 planes [px][C]. out mode 0: fp32 NCHW; mode 1: fp16 planes.
// =====================================================================
#define SINW (324 * 12)
#define MMA_SW (9 * 4 * 32)
#define MMA_SMEM (2 * SINW * 4 + 2 * MMA_SW * 16)

template <int NF>
__global__ void __launch_bounds__(256, 2) conv_mma_s1(
    const unsigned short* __restrict__ in, const uint4* __restrict__ wp,
    const float* __restrict__ bias, float* __restrict__ fout,
    unsigned short* __restrict__ bout, int C, int OC, int H, int W, int act, int mode)
{
    const int KC = C >> 4;
    const int tilesX = W >> 4;
    const int x0 = (blockIdx.x % tilesX) << 4;
    const int y0 = (blockIdx.x / tilesX) << 4;
    const int oc0 = blockIdx.y * (NF * 8);
    const int b = blockIdx.z;
    const int OCg = OC >> 3;

    extern __shared__ __align__(16) unsigned char dsm[];
    unsigned* s_in = (unsigned*)dsm;
    uint4* s_w = (uint4*)(dsm + 2 * SINW * 4);

    const unsigned short* inb = in + (size_t)b * H * W * C;
    const int tid = threadIdx.x, lane = tid & 31, wid = tid >> 5;
    const int g = lane >> 2, tg = lane & 3;

    float d[2][NF][4];
#pragma unroll
    for (int i = 0; i < 2; i++)
#pragma unroll
        for (int j = 0; j < NF; j++)
#pragma unroll
            for (int r = 0; r < 4; r++) d[i][j][r] = 0.f;

    auto stage = [&](int buf, int kc) {
        unsigned* si = s_in + buf * SINW;
        for (int i = tid; i < 648; i += 256) {
            int sp = i >> 1, q = i & 1;
            int r = sp / 18, c = sp - r * 18;
            int iy = y0 - 1 + r, ix = x0 - 1 + c;
            bool p = (unsigned)iy < (unsigned)H && (unsigned)ix < (unsigned)W;
            const unsigned short* src = inb + ((size_t)iy * W + ix) * C + (kc << 4) + (q << 3);
            cp_async16(si + sp * 12 + q * 4, src, p);
        }
        uint4* sw = s_w + buf * MMA_SW;
        const uint4* wsrc = wp + (size_t)kc * 9 * OCg * 32;
        const int tot = 9 * NF * 32;
        for (int i = tid; i < tot; i += 256) {
            int l = i & 31;
            int q = i >> 5;
            int ogl = q % NF;
            int t = q / NF;
            cp_async16(sw + (t * 4 + ogl) * 32 + l,
                       wsrc + ((size_t)t * OCg + (oc0 >> 3) + ogl) * 32 + l, true);
        }
    };

    auto compute = [&](int buf) {
        unsigned* si = s_in + buf * SINW;
        uint4* sw = s_w + buf * MMA_SW;
#pragma unroll
        for (int t = 0; t < 9; t++) {
            const int dy = t / 3, dx = t - 3 * (t / 3);
            unsigned ah[2][4];
#pragma unroll
            for (int i = 0; i < 2; i++) {
                int sp0 = (2 * wid + i + dy) * 18 + g + dx;
                const unsigned* h0 = si + sp0 * 12;
                ah[i][0] = h0[tg];       ah[i][1] = h0[96 + tg];
                ah[i][2] = h0[tg + 4];   ah[i][3] = h0[96 + tg + 4];
            }
#pragma unroll
            for (int j = 0; j < NF; j++) {
                uint4 bw = sw[(t * 4 + j) * 32 + lane];
#pragma unroll
                for (int i = 0; i < 2; i++) {
                    mma16816(d[i][j], ah[i], bw.x, bw.y);
                }
            }
        }
    };

    stage(0, 0);
    cp_commit();
    for (int kc = 0; kc < KC; kc++) {
        int buf = kc & 1;
        cp_wait0();
        __syncthreads();
        if (kc + 1 < KC) stage(buf ^ 1, kc + 1);
        cp_commit();
        compute(buf);
    }

    if (mode == 0) {
#pragma unroll
        for (int i = 0; i < 2; i++) {
            int y = y0 + 2 * wid + i;
#pragma unroll
            for (int j = 0; j < NF; j++) {
                int oc = oc0 + 8 * j + 2 * tg;
                float b0 = bias[oc], b1 = bias[oc + 1];
                size_t base0 = (((size_t)b * OC + oc) * H + y) * W + x0;
                size_t base1 = base0 + (size_t)H * W;
                fout[base0 + g]     = activate(d[i][j][0] + b0, act);
                fout[base1 + g]     = activate(d[i][j][1] + b1, act);
                fout[base0 + g + 8] = activate(d[i][j][2] + b0, act);
                fout[base1 + g + 8] = activate(d[i][j][3] + b1, act);
            }
        }
    } else {
        unsigned short* bo = bout + (size_t)b * H * W * OC;
#pragma unroll
        for (int i = 0; i < 2; i++) {
            int y = y0 + 2 * wid + i;
#pragma unroll
            for (int j = 0; j < NF; j++) {
                int oc = oc0 + 8 * j + 2 * tg;
                float b0 = bias[oc], b1 = bias[oc + 1];
                float v0 = activate(d[i][j][0] + b0, act);
                float v1 = activate(d[i][j][1] + b1, act);
                float v2 = activate(d[i][j][2] + b0, act);
                float v3 = activate(d[i][j][3] + b1, act);
                size_t px0 = (size_t)y * W + x0 + g;
                size_t px1 = px0 + 8;
                *(unsigned*)(bo + px0 * OC + oc) = pack2_f16(v0, v1);
                *(unsigned*)(bo + px1 * OC + oc) = pack2_f16(v2, v3);
            }
        }
    }
}

// =====================================================================
// s2c stride-2 conv (fp16 single-term). Tap skip by k-chunk phase.
// =====================================================================
#define SINW2 (289 * 12)
#define MMA_SW2 (4 * 4 * 32)
#define MMA_SMEM2 (2 * SINW2 * 4 + 2 * MMA_SW2 * 16)

template <int NF>
__global__ void __launch_bounds__(256, 2) conv_mma_s2c(
    const unsigned short* __restrict__ in, const uint4* __restrict__ wp,
    const float* __restrict__ bias, float* __restrict__ fout,
    unsigned short* __restrict__ bout, int C, int OC, int Hout, int Wout,
    int act, int mode)
{
    const int CC = 4 * C;
    const int KC = CC >> 4;
    const int Hin = Hout * 2, Win = Wout * 2;
    const int tilesX = Wout >> 4;
    const int x0 = (blockIdx.x % tilesX) << 4;
    const int y0 = (blockIdx.x / tilesX) << 4;
    const int oc0 = blockIdx.y * (NF * 8);
    const int b = blockIdx.z;
    const int OCg = OC >> 3;

    extern __shared__ __align__(16) unsigned char dsm[];
    unsigned* s_in = (unsigned*)dsm;
    uint4* s_w = (uint4*)(dsm + 2 * SINW2 * 4);

    const unsigned short* inb = in + (size_t)b * Hin * Win * C;
    const int tid = threadIdx.x, lane = tid & 31, wid = tid >> 5;
    const int g = lane >> 2, tg = lane & 3;

    float d[2][NF][4];
#pragma unroll
    for (int i = 0; i < 2; i++)
#pragma unroll
        for (int j = 0; j < NF; j++)
#pragma unroll
            for (int r = 0; r < 4; r++) d[i][j][r] = 0.f;

    auto stage = [&](int buf, int kc) {
        unsigned* si = s_in + buf * SINW2;
        int qph = (kc << 4) / C;
        int c0 = (kc << 4) - qph * C;
        int pa = qph >> 1, pb = qph & 1;
        for (int i = tid; i < 578; i += 256) {
            int sp = i >> 1, q = i & 1;
            int r = sp / 17, c = sp - r * 17;
            int sy = 2 * (y0 + r) + pa, sx = 2 * (x0 + c) + pb;
            bool p = sy < Hin && sx < Win;
            const unsigned short* src = inb + ((size_t)sy * Win + sx) * C + c0 + (q << 3);
            cp_async16(si + sp * 12 + q * 4, src, p);
        }
        uint4* sw = s_w + buf * MMA_SW2;
        const uint4* wsrc = wp + (size_t)kc * 4 * OCg * 32;
        const int tot = 4 * NF * 32;
        for (int i = tid; i < tot; i += 256) {
            int l = i & 31;
            int q = i >> 5;
            int ogl = q % NF;
            int t = q / NF;
            cp_async16(sw + (t * 4 + ogl) * 32 + l,
                       wsrc + ((size_t)t * OCg + (oc0 >> 3) + ogl) * 32 + l, true);
        }
    };

    auto compute = [&](int buf, int pa, int pb) {
        unsigned* si = s_in + buf * SINW2;
        uint4* sw = s_w + buf * MMA_SW2;
#pragma unroll
        for (int t = 0; t < 4; t++) {
            const int dy = t >> 1, dx = t & 1;
            if ((dy && pa) || (dx && pb)) continue;
            unsigned ah[2][4];
#pragma unroll
            for (int i = 0; i < 2; i++) {
                int sp0 = (2 * wid + i + dy) * 17 + g + dx;
                const unsigned* h0 = si + sp0 * 12;
                ah[i][0] = h0[tg];       ah[i][1] = h0[96 + tg];
                ah[i][2] = h0[tg + 4];   ah[i][3] = h0[96 + tg + 4];
            }
#pragma unroll
            for (int j = 0; j < NF; j++) {
                uint4 bw = sw[(t * 4 + j) * 32 + lane];
#pragma unroll
                for (int i = 0; i < 2; i++) {
                    mma16816(d[i][j], ah[i], bw.x, bw.y);
                }
            }
        }
    };

    stage(0, 0);
    cp_commit();
    for (int kc = 0; kc < KC; kc++) {
        int buf = kc & 1;
        cp_wait0();
        __syncthreads();
        if (kc + 1 < KC) stage(buf ^ 1, kc + 1);
        cp_commit();
        int qc = (kc << 4) / C;
        compute(buf, qc >> 1, qc & 1);
    }

    if (mode == 0) {
#pragma unroll
        for (int i = 0; i < 2; i++) {
            int y = y0 + 2 * wid + i;
#pragma unroll
            for (int j = 0; j < NF; j++) {
                int oc = oc0 + 8 * j + 2 * tg;
                float b0 = bias[oc], b1 = bias[oc + 1];
                size_t base0 = (((size_t)b * OC + oc) * Hout + y) * Wout + x0;
                size_t base1 = base0 + (size_t)Hout * Wout;
                fout[base0 + g]     = activate(d[i][j][0] + b0, act);
                fout[base1 + g]     = activate(d[i][j][1] + b1, act);
                fout[base0 + g + 8] = activate(d[i][j][2] + b0, act);
                fout[base1 + g + 8] = activate(d[i][j][3] + b1, act);
            }
        }
    } else {
        unsigned short* bo = bout + (size_t)b * Hout * Wout * OC;
#pragma unroll
        for (int i = 0; i < 2; i++) {
            int y = y0 + 2 * wid + i;
#pragma unroll
            for (int j = 0; j < NF; j++) {
                int oc = oc0 + 8 * j + 2 * tg;
                float b0 = bias[oc], b1 = bias[oc + 1];
                float v0 = activate(d[i][j][0] + b0, act);
                float v1 = activate(d[i][j][1] + b1, act);
                float v2 = activate(d[i][j][2] + b0, act);
                float v3 = activate(d[i][j][3] + b1, act);
                size_t px0 = (size_t)y * Wout + x0 + g;
                size_t px1 = px0 + 8;
                *(unsigned*)(bo + px0 * OC + oc) = pack2_f16(v0, v1);
                *(unsigned*)(bo + px1 * OC + oc) = pack2_f16(v2, v3);
            }
        }
    }
}

// =====================================================================
// t2c transposed conv (fp16 single-term). Tap skip per fragment phase. relu.
// =====================================================================
template <int NF>
__global__ void __launch_bounds__(256, 2) conv_mma_t2c(
    const unsigned short* __restrict__ in, const uint4* __restrict__ wp,
    const float* __restrict__ bias, unsigned short* __restrict__ bout,
    int C, int OC, int Hin, int Win)
{
    const int KC = C >> 4;
    const int NN = 4 * OC;
    const int OCgN = NN >> 3;
    const int Wout = Win * 2;
    const int tilesX = Win >> 4;
    const int x0 = (blockIdx.x % tilesX) << 4;
    const int y0 = (blockIdx.x / tilesX) << 4;
    const int oc0 = blockIdx.y * (NF * 8);
    const int b = blockIdx.z;

    extern __shared__ __align__(16) unsigned char dsm[];
    unsigned* s_in = (unsigned*)dsm;
    uint4* s_w = (uint4*)(dsm + 2 * SINW2 * 4);

    const unsigned short* inb = in + (size_t)b * Hin * Win * C;
    const int tid = threadIdx.x, lane = tid & 31, wid = tid >> 5;
    const int g = lane >> 2, tg = lane & 3;

    int aj[NF], bj[NF];
#pragma unroll
    for (int j = 0; j < NF; j++) {
        int qj = (oc0 + 8 * j) / OC;
        aj[j] = qj >> 1;
        bj[j] = qj & 1;
    }

    float d[2][NF][4];
#pragma unroll
    for (int i = 0; i < 2; i++)
#pragma unroll
        for (int j = 0; j < NF; j++)
#pragma unroll
            for (int r = 0; r < 4; r++) d[i][j][r] = 0.f;

    auto stage = [&](int buf, int kc) {
        unsigned* si = s_in + buf * SINW2;
        for (int i = tid; i < 578; i += 256) {
            int sp = i >> 1, q = i & 1;
            int r = sp / 17, c = sp - r * 17;
            int iy = y0 - 1 + r, ix = x0 - 1 + c;
            bool p = (unsigned)iy < (unsigned)Hin && (unsigned)ix < (unsigned)Win;
            const unsigned short* src = inb + ((size_t)iy * Win + ix) * C + (kc << 4) + (q << 3);
            cp_async16(si + sp * 12 + q * 4, src, p);
        }
        uint4* sw = s_w + buf * MMA_SW2;
        const uint4* wsrc = wp + (size_t)kc * 4 * OCgN * 32;
        const int tot = 4 * NF * 32;
        for (int i = tid; i < tot; i += 256) {
            int l = i & 31;
            int q = i >> 5;
            int ogl = q % NF;
            int t = q / NF;
            cp_async16(sw + (t * 4 + ogl) * 32 + l,
                       wsrc + ((size_t)t * OCgN + (oc0 >> 3) + ogl) * 32 + l, true);
        }
    };

    auto compute = [&](int buf) {
        unsigned* si = s_in + buf * SINW2;
        uint4* sw = s_w + buf * MMA_SW2;
#pragma unroll
        for (int t = 0; t < 4; t++) {
            const int dy = t >> 1, dx = t & 1;
            unsigned ah[2][4];
#pragma unroll
            for (int i = 0; i < 2; i++) {
                int sp0 = (2 * wid + i + dy) * 17 + g + dx;
                const unsigned* h0 = si + sp0 * 12;
                ah[i][0] = h0[tg];       ah[i][1] = h0[96 + tg];
                ah[i][2] = h0[tg + 4];   ah[i][3] = h0[96 + tg + 4];
            }
#pragma unroll
            for (int j = 0; j < NF; j++) {
                if ((dy == 0 && aj[j]) || (dx == 0 && bj[j])) continue;
                uint4 bw = sw[(t * 4 + j) * 32 + lane];
#pragma unroll
                for (int i = 0; i < 2; i++) {
                    mma16816(d[i][j], ah[i], bw.x, bw.y);
                }
            }
        }
    };

    stage(0, 0);
    cp_commit();
    for (int kc = 0; kc < KC; kc++) {
        int buf = kc & 1;
        cp_wait0();
        __syncthreads();
        if (kc + 1 < KC) stage(buf ^ 1, kc + 1);
        cp_commit();
        compute(buf);
    }

    unsigned short* bo2 = bout + (size_t)b * (2 * Hin) * Wout * OC;
#pragma unroll
    for (int i = 0; i < 2; i++) {
        int yin = y0 + 2 * wid + i;
#pragma unroll
        for (int j = 0; j < NF; j++) {
            int n0 = oc0 + 8 * j + 2 * tg;
            int q = n0 / OC;
            int oc = n0 - q * OC;
            int a = q >> 1, bph = q & 1;
            int oy = 2 * yin + a;
            float b0 = bias[oc], b1 = bias[oc + 1];
            float v0 = d[i][j][0] + b0; v0 = v0 > 0.f ? v0 : 0.f;
            float v1 = d[i][j][1] + b1; v1 = v1 > 0.f ? v1 : 0.f;
            float v2 = d[i][j][2] + b0; v2 = v2 > 0.f ? v2 : 0.f;
            float v3 = d[i][j][3] + b1; v3 = v3 > 0.f ? v3 : 0.f;
            size_t px0 = (size_t)oy * Wout + 2 * (x0 + g) + bph;
            size_t px1 = (size_t)oy * Wout + 2 * (x0 + g + 8) + bph;
            *(unsigned*)(bo2 + px0 * OC + oc) = pack2_f16(v0, v1);
            *(unsigned*)(bo2 + px1 * OC + oc) = pack2_f16(v2, v3);
        }
    }
}

// ---------------- keypoint bottleneck ----------------
__global__ void bn_stats(const float* __restrict__ R, float* __restrict__ S,
                         float* __restrict__ Sh, float* __restrict__ Sw)
{
    int bk = blockIdx.x;
    int t = threadIdx.x;
    float v = R[(size_t)bk * 256 + t];
    float a = v;
    float bsum = v * (float)(t >> 4);
    float c = v * (float)(t & 15);
#pragma unroll
    for (int off = 16; off > 0; off >>= 1) {
        a += __shfl_down_sync(0xffffffffu, a, off);
        bsum += __shfl_down_sync(0xffffffffu, bsum, off);
        c += __shfl_down_sync(0xffffffffu, c, off);
    }
    __shared__ float sa[8], sb[8], sc[8];
    int wid = t >> 5;
    if ((t & 31) == 0) { sa[wid] = a; sb[wid] = bsum; sc[wid] = c; }
    __syncthreads();
    if (t == 0) {
        float ta = 0.f, tb = 0.f, tc = 0.f;
        for (int i = 0; i < 8; i++) { ta += sa[i]; tb += sb[i]; tc += sc[i]; }
        S[bk] = ta; Sh[bk] = tb; Sw[bk] = tc;
    }
}

// maps -> fp16 planes [px][128]; grid (32, 16), block 256
__global__ void bn_maps(const float* __restrict__ S, const float* __restrict__ Sh,
                        const float* __restrict__ Sw, unsigned short* __restrict__ bout)
{
    int b = blockIdx.x;
    int spc = blockIdx.y;
    int k = threadIdx.x & 127;
    int half = threadIdx.x >> 7;
    float s = S[b * 128 + k];
    float denom = S[b * 128 + 127];
    float mu = s * (1.f / 256.f);
    float inv = 1.f / denom;
    float c0 = Sh[b * 128 + k] * inv;
    float c1 = Sw[b * 128 + k] * inv;
    unsigned short* bo = bout + (size_t)b * 256 * 128;
#pragma unroll
    for (int i = 0; i < 8; i++) {
        int sp = spc * 16 + half * 8 + i;
        float dh = (float)(sp >> 4) - c0;
        float dw = (float)(sp & 15) - c1;
        float v = mu * expf(-0.5f * (dh * dh + dw * dw));
        bo[sp * 128 + k] = f16_us(v);
    }
}

// ---------------- launch ----------------
extern "C" void kernel_launch(void* const* d_in, const int* in_sizes, int n_in,
                              void* d_out, int out_size)
{
    (void)in_sizes; (void)n_in; (void)out_size;
    const float* x = (const float*)d_in[0];
    const float* ew[7]; const float* eb[7];
    for (int j = 0; j < 7; j++) {
        ew[j] = (const float*)d_in[1 + 2 * j];
        eb[j] = (const float*)d_in[2 + 2 * j];
    }
    const float* dw[6]; const float* db[6];
    for (int j = 0; j < 6; j++) {
        dw[j] = (const float*)d_in[15 + 2 * j];
        db[j] = (const float*)d_in[16 + 2 * j];
    }
    float* out = (float*)d_out;

    float *F1, *S, *Sh, *Sw;
    unsigned short *B0, *B1;
    uint4 *wprep, *wprep0, *wprep2, *wprep3;
    cudaGetSymbolAddress((void**)&F1, g_f1);
    cudaGetSymbolAddress((void**)&B0, g_b0);
    cudaGetSymbolAddress((void**)&B1, g_b1);
    cudaGetSymbolAddress((void**)&wprep, g_wprep);
    cudaGetSymbolAddress((void**)&wprep0, g_wprep0);
    cudaGetSymbolAddress((void**)&wprep2, g_wprep2);
    cudaGetSymbolAddress((void**)&wprep3, g_wprep3);
    cudaGetSymbolAddress((void**)&S, g_S);
    cudaGetSymbolAddress((void**)&Sh, g_Sh);
    cudaGetSymbolAddress((void**)&Sw, g_Sw);

    static bool attr_set = false;
    if (!attr_set) {
        cudaFuncSetAttribute(conv_mma_s1<4>, cudaFuncAttributeMaxDynamicSharedMemorySize, MMA_SMEM);
        cudaFuncSetAttribute(conv_mma_s1<2>, cudaFuncAttributeMaxDynamicSharedMemorySize, MMA_SMEM);
        cudaFuncSetAttribute(conv_mma_s2c<4>, cudaFuncAttributeMaxDynamicSharedMemorySize, MMA_SMEM2);
        cudaFuncSetAttribute(conv_mma_s2c<2>, cudaFuncAttributeMaxDynamicSharedMemorySize, MMA_SMEM2);
        cudaFuncSetAttribute(conv_mma_t2c<4>, cudaFuncAttributeMaxDynamicSharedMemorySize, MMA_SMEM2);
        cudaFuncSetAttribute(conv_mma_t2c<2>, cudaFuncAttributeMaxDynamicSharedMemorySize, MMA_SMEM2);
        attr_set = true;
    }

    const int B = 32;
    const int OFF_E1 = 0, OFF_E3 = 2304, OFF_E5 = 11520;
    const int OFF_D1 = 48384, OFF_D3 = 57600, OFF_D5 = 59904;
    const int OFF2_E2 = 0, OFF2_E4 = 8192, OFF2_E6 = 40960;
    const int OFF3_D0 = 0, OFF3_D2 = 32768, OFF3_D4 = 40960;

    prep_many<<<dim3(144, 3, 1), 256>>>(ew[1], ew[3], ew[5], wprep,
                                        OFF_E1, OFF_E3, OFF_E5, 32, 32, 64, 64, 128, 128);
    prep_many<<<dim3(36, 3, 1), 256>>>(dw[1], dw[3], dw[5], wprep,
                                       OFF_D1, OFF_D3, OFF_D5, 64, 64, 32, 32, 16, 16);
    prep_s2c<<<dim3(256, 3, 1), 256>>>(ew[2], ew[4], ew[6], wprep2,
                                       OFF2_E2, OFF2_E4, OFF2_E6,
                                       32, 64, 64, 128, 128, 128);
    prep_t2c<<<dim3(128, 3, 1), 256>>>(dw[0], dw[2], dw[4], wprep3,
                                       OFF3_D0, OFF3_D2, OFF3_D4,
                                       128, 64, 64, 32, 32, 16);
    prep_e0<<<dim3(5, 1, 1), 256>>>(ew[0], wprep0);

    // ---- encoder ----
    x2half<<<dim3(2048, 1, 1), 256>>>(x, B0);
    // e0 as mma: B0 (C=16 padded) -> B1
    conv_mma_s1<4><<<dim3(64, 1, B), 256, MMA_SMEM>>>(B0, wprep0, eb[0],
                                                      nullptr, B1, 16, 32, 128, 128, 0, 1);
    // e1: B1 -> B0
    conv_mma_s1<4><<<dim3(64, 1, B), 256, MMA_SMEM>>>(B1, wprep + OFF_E1, eb[1],
                                                      nullptr, B0, 32, 32, 128, 128, 0, 1);
    // e2: B0 -> B1
    conv_mma_s2c<4><<<dim3(16, 2, B), 256, MMA_SMEM2>>>(B0, wprep2 + OFF2_E2, eb[2],
                                                        nullptr, B1, 32, 64, 64, 64, 1, 1);
    // e3: B1 -> B0
    conv_mma_s1<4><<<dim3(16, 2, B), 256, MMA_SMEM>>>(B1, wprep + OFF_E3, eb[3],
                                                      nullptr, B0, 64, 64, 64, 64, 1, 1);
    // e4: B0 -> B1
    conv_mma_s2c<4><<<dim3(4, 4, B), 256, MMA_SMEM2>>>(B0, wprep2 + OFF2_E4, eb[4],
                                                       nullptr, B1, 64, 128, 32, 32, 1, 1);
    // e5: B1 -> B0
    conv_mma_s1<4><<<dim3(4, 4, B), 256, MMA_SMEM>>>(B1, wprep + OFF_E5, eb[5],
                                                     nullptr, B0, 128, 128, 32, 32, 1, 1);
    // e6: B0 -> F1 (fp32 NCHW, softplus)
    conv_mma_s2c<2><<<dim3(1, 8, B), 256, MMA_SMEM2>>>(B0, wprep2 + OFF2_E6, eb[6],
                                                       F1, nullptr, 128, 128, 16, 16, 3, 0);
    // ---- keypoint bottleneck ----
    bn_stats<<<4096, 256>>>(F1, S, Sh, Sw);
    bn_maps<<<dim3(32, 16, 1), 256>>>(S, Sh, Sw, B0);
    // ---- decoder ----
    conv_mma_t2c<2><<<dim3(1, 16, B), 256, MMA_SMEM2>>>(B0, wprep3 + OFF3_D0, db[0],
                                                        B1, 128, 64, 16, 16);
    conv_mma_s1<4><<<dim3(4, 2, B), 256, MMA_SMEM>>>(B1, wprep + OFF_D1, db[1],
                                                     nullptr, B0, 64, 64, 32, 32, 2, 1);
    conv_mma_t2c<4><<<dim3(4, 4, B), 256, MMA_SMEM2>>>(B0, wprep3 + OFF3_D2, db[2],
                                                       B1, 64, 32, 32, 32);
    conv_mma_s1<4><<<dim3(16, 1, B), 256, MMA_SMEM>>>(B1, wprep + OFF_D3, db[3],
                                                      nullptr, B0, 32, 32, 64, 64, 2, 1);
    conv_mma_t2c<4><<<dim3(16, 2, B), 256, MMA_SMEM2>>>(B0, wprep3 + OFF3_D4, db[4],
                                                        B1, 32, 16, 64, 64);
    conv_mma_s1<2><<<dim3(64, 1, B), 256, MMA_SMEM>>>(B1, wprep + OFF_D5, db[5],
                                                      out, nullptr, 16, 16, 128, 128, 2, 0);
}